// round 8
// baseline (speedup 1.0000x reference)
#include <cuda_runtime.h>
#include <math.h>
#include <stdint.h>

typedef unsigned long long ull;

#define KA 12
#define HSZ 4608
#define INP 5024
#define EPSB 1e-5f
#define NPX 6912.f

// big gemm tiling: 8 chunks x 628 cols, 108 row-blocks x 128 rows
#define CSZ 628
#define CPAD 640
#define LSTR 640
#define NCH 8
#define NRB 108
// head gemm tiling
#define CSZ2 768
#define LSTR2 770
#define NCH2 6
#define HROWS 320

// scratch
__device__ __align__(16) float g_h1[KA*16*576];
__device__ __align__(16) float g_h2[KA*16*576];
__device__ __align__(16) float g_h3[KA*8*576];
__device__ float g_p1[72*16*2];
__device__ float g_p2[72*16*2];
__device__ float g_p3[72*8*2];
__device__ float g_op[192], g_om[192], g_mm[192];
__device__ __align__(16) float g_part[(size_t)NCH*13824*KA];
__device__ __align__(16) float g_hp[6*HSZ*2];
__device__ __align__(16) float g_part2[(size_t)NCH2*HROWS*KA];

__device__ __forceinline__ ull pk2(float a, float b){ ull r; asm("mov.b64 %0,{%1,%2};":"=l"(r):"f"(a),"f"(b)); return r; }
__device__ __forceinline__ ull dup2(float a){ ull r; asm("mov.b64 %0,{%1,%1};":"=l"(r):"f"(a)); return r; }
__device__ __forceinline__ ull fma2(ull a, ull b, ull c){ ull d; asm("fma.rn.f32x2 %0,%1,%2,%3;":"=l"(d):"l"(a),"l"(b),"l"(c)); return d; }
__device__ __forceinline__ ull add2(ull a, ull b){ ull d; asm("add.rn.f32x2 %0,%1,%2;":"=l"(d):"l"(a),"l"(b)); return d; }

// ---------- conv1: 1x1 over (c,d) (bias cancels in BN) + stats; block(0,0) also agent linears ----------
__global__ __launch_bounds__(96) void k_conv1(const float* __restrict__ x,
                                              const float* __restrict__ w1,
                                              const float* __restrict__ p,  const float* __restrict__ m,
                                              const float* __restrict__ phys_w, const float* __restrict__ phys_b,
                                              const float* __restrict__ ment_w, const float* __restrict__ ment_b){
    __shared__ float ws[4096];
    __shared__ float sred[3][16][2];
    int b = blockIdx.x, strip = blockIdx.y, tid = threadIdx.x;
    int warp = tid>>5, lane = tid&31;
    for (int i = tid; i < 4096; i += 96) ws[i] = w1[i];
    __syncthreads();
    int px = strip*96 + tid;
    float acc[16];
#pragma unroll
    for (int o = 0; o < 16; o++) acc[o] = 0.f;
    const float* xb = x + (size_t)b*147456 + px;
#pragma unroll 16
    for (int cd = 0; cd < 256; cd++){
        float xv = xb[(size_t)cd*576];
#pragma unroll
        for (int o = 0; o < 16; o++) acc[o] += xv * ws[o*256+cd];
    }
#pragma unroll
    for (int o = 0; o < 16; o++) g_h1[((size_t)b*16+o)*576 + px] = acc[o];
#pragma unroll
    for (int o = 0; o < 16; o++){
        float s = acc[o], q = acc[o]*acc[o];
#pragma unroll
        for (int off = 16; off; off >>= 1){
            s += __shfl_xor_sync(0xffffffffu, s, off);
            q += __shfl_xor_sync(0xffffffffu, q, off);
        }
        if (lane == 0){ sred[warp][o][0] = s; sred[warp][o][1] = q; }
    }
    __syncthreads();
    if (tid < 16){
        int blk = b*6 + strip;
        g_p1[blk*32 + tid*2+0] = sred[0][tid][0]+sred[1][tid][0]+sred[2][tid][0];
        g_p1[blk*32 + tid*2+1] = sred[0][tid][1]+sred[1][tid][1]+sred[2][tid][1];
    }
    if (b == 0 && strip == 0){
        for (int i = tid; i < 192; i += 96){
            int j = i/16, t = i%16;
            float s1 = phys_b[t], s2 = ment_b[t], s3 = ment_b[t];
            for (int k = 0; k < 16; k++){
                s1 += p[j*16+k] * phys_w[t*16+k];
                float mv = m[j*16+k];
                s2 += mv * ment_w[t*16+k];
                s3 += 0.9f * mv * ment_w[t*16+k];
            }
            g_op[i] = fmaxf(s1, 0.f);
            g_om[i] = fmaxf(s2, 0.f);
            g_mm[i] = fmaxf(s3, 0.f);
        }
    }
}

// ---------- conv2: bn1 from partials + relu -> 3x3 SAME + stats (4-row strips) ----------
__global__ __launch_bounds__(96) void k_conv2(const float* __restrict__ w2,
                                              const float* __restrict__ g1,
                                              const float* __restrict__ bb1){
    __shared__ float in_s[16][6][24];
    __shared__ float ws[2304];
    __shared__ float sc[16], sh[16];
    __shared__ float sred[3][16][2];
    int b = blockIdx.x, ty = blockIdx.y, tid = threadIdx.x;
    int warp = tid>>5, lane = tid&31;
    if (tid < 16){
        float S = 0.f, Q = 0.f;
#pragma unroll
        for (int i = 0; i < 72; i++){ S += g_p1[i*32+tid*2]; Q += g_p1[i*32+tid*2+1]; }
        float mu = S/NPX, var = Q/NPX - mu*mu;
        float r = rsqrtf(var + EPSB) * g1[tid];
        sc[tid] = r; sh[tid] = bb1[tid] - mu*r;
    }
    for (int i = tid; i < 2304; i += 96) ws[i] = w2[i];
    __syncthreads();
    int r0 = 4*ty - 1;
    for (int i = tid; i < 16*6*24; i += 96){
        int ci = i/144, rr = (i/24)%6, cc = i%24;
        int gy = r0 + rr; float v = 0.f;
        if (gy >= 0 && gy < 24)
            v = fmaxf(g_h1[((size_t)b*16+ci)*576 + gy*24 + cc]*sc[ci] + sh[ci], 0.f);
        in_s[ci][rr][cc] = v;
    }
    __syncthreads();
    int ly = tid/24, lx = tid%24, gy = 4*ty + ly;
    float acc[16];
#pragma unroll
    for (int o = 0; o < 16; o++) acc[o] = 0.f;
    for (int ci = 0; ci < 16; ci++){
#pragma unroll
        for (int ky = 0; ky < 3; ky++){
#pragma unroll
            for (int kx = 0; kx < 3; kx++){
                int gx = lx + kx - 1;
                if (gx >= 0 && gx < 24){
                    float xv = in_s[ci][ly+ky][gx];
#pragma unroll
                    for (int o = 0; o < 16; o++) acc[o] += xv * ws[(o*16+ci)*9 + ky*3 + kx];
                }
            }
        }
    }
#pragma unroll
    for (int o = 0; o < 16; o++) g_h2[((size_t)b*16+o)*576 + gy*24 + lx] = acc[o];
#pragma unroll
    for (int o = 0; o < 16; o++){
        float s = acc[o], q = acc[o]*acc[o];
#pragma unroll
        for (int off = 16; off; off >>= 1){
            s += __shfl_xor_sync(0xffffffffu, s, off);
            q += __shfl_xor_sync(0xffffffffu, q, off);
        }
        if (lane == 0){ sred[warp][o][0] = s; sred[warp][o][1] = q; }
    }
    __syncthreads();
    if (tid < 16){
        int blk = b*6 + ty;
        g_p2[blk*32 + tid*2+0] = sred[0][tid][0]+sred[1][tid][0]+sred[2][tid][0];
        g_p2[blk*32 + tid*2+1] = sred[0][tid][1]+sred[1][tid][1]+sred[2][tid][1];
    }
}

// ---------- conv3: bn2 from partials + relu -> 5x5 SAME + stats (4-row strips) ----------
__global__ __launch_bounds__(96) void k_conv3(const float* __restrict__ w3,
                                              const float* __restrict__ g2,
                                              const float* __restrict__ bb2){
    __shared__ float in_s[16][8][24];
    __shared__ float ws[3200];
    __shared__ float sc[16], sh[16];
    __shared__ float sred[3][8][2];
    int b = blockIdx.x, ty = blockIdx.y, tid = threadIdx.x;
    int warp = tid>>5, lane = tid&31;
    if (tid < 16){
        float S = 0.f, Q = 0.f;
#pragma unroll
        for (int i = 0; i < 72; i++){ S += g_p2[i*32+tid*2]; Q += g_p2[i*32+tid*2+1]; }
        float mu = S/NPX, var = Q/NPX - mu*mu;
        float r = rsqrtf(var + EPSB) * g2[tid];
        sc[tid] = r; sh[tid] = bb2[tid] - mu*r;
    }
    for (int i = tid; i < 3200; i += 96) ws[i] = w3[i];
    __syncthreads();
    int r0 = 4*ty - 2;
    for (int i = tid; i < 16*8*24; i += 96){
        int ci = i/192, rr = (i/24)%8, cc = i%24;
        int gy = r0 + rr; float v = 0.f;
        if (gy >= 0 && gy < 24)
            v = fmaxf(g_h2[((size_t)b*16+ci)*576 + gy*24 + cc]*sc[ci] + sh[ci], 0.f);
        in_s[ci][rr][cc] = v;
    }
    __syncthreads();
    int ly = tid/24, lx = tid%24, gy = 4*ty + ly;
    float acc[8];
#pragma unroll
    for (int o = 0; o < 8; o++) acc[o] = 0.f;
    for (int ci = 0; ci < 16; ci++){
#pragma unroll
        for (int ky = 0; ky < 5; ky++){
#pragma unroll
            for (int kx = 0; kx < 5; kx++){
                int gx = lx + kx - 2;
                if (gx >= 0 && gx < 24){
                    float xv = in_s[ci][ly+ky][gx];
#pragma unroll
                    for (int o = 0; o < 8; o++) acc[o] += xv * ws[(o*16+ci)*25 + ky*5 + kx];
                }
            }
        }
    }
#pragma unroll
    for (int o = 0; o < 8; o++) g_h3[((size_t)b*8+o)*576 + gy*24 + lx] = acc[o];
#pragma unroll
    for (int o = 0; o < 8; o++){
        float s = acc[o], q = acc[o]*acc[o];
#pragma unroll
        for (int off = 16; off; off >>= 1){
            s += __shfl_xor_sync(0xffffffffu, s, off);
            q += __shfl_xor_sync(0xffffffffu, q, off);
        }
        if (lane == 0){ sred[warp][o][0] = s; sred[warp][o][1] = q; }
    }
    __syncthreads();
    if (tid < 8){
        int blk = b*6 + ty;
        g_p3[blk*16 + tid*2+0] = sred[0][tid][0]+sred[1][tid][0]+sred[2][tid][0];
        g_p3[blk*16 + tid*2+1] = sred[0][tid][1]+sred[1][tid][1]+sred[2][tid][1];
    }
}

__device__ __forceinline__ void ldw(float2 W[4], const float* wr, int c, bool ok){
    if (ok){
        W[0] = *(const float2*)(wr + c);
        W[1] = *(const float2*)(wr + INP + c);
        W[2] = *(const float2*)(wr + 2*INP + c);
        W[3] = *(const float2*)(wr + 3*INP + c);
    } else {
        W[0] = W[1] = W[2] = W[3] = make_float2(0.f, 0.f);
    }
}

// ---------- big weight-streaming GEMM (i,g,o rows; f gate dead since c0=0) ----------
// grid (108, 8) x 128 thr. 128 rows/block (8 passes x 4 warps x 4 rows).
__global__ __launch_bounds__(128) void k_gemm(
    const float* __restrict__ w_ih, const float* __restrict__ g3,
    const float* __restrict__ bb3,  const float* __restrict__ vis)
{
    __shared__ __align__(16) ull ls[6*LSTR];
    __shared__ float sc[8], sh[8];
    const int rblk = blockIdx.x, chunk = blockIdx.y, tid = threadIdx.x;
    const int c0 = chunk * CSZ;
    if (tid < 8){
        float S = 0.f, Q = 0.f;
#pragma unroll
        for (int i = 0; i < 72; i++){ S += g_p3[i*16+tid*2]; Q += g_p3[i*16+tid*2+1]; }
        float mu = S/NPX, var = Q/NPX - mu*mu;
        float r = rsqrtf(var + EPSB) * g3[tid];
        sc[tid] = r; sh[tid] = bb3[tid] - mu*r;
    }
    __syncthreads();
    // fill: agent-pair-packed lstm_in slice with zero pad for c >= CSZ
    for (int i = tid; i < 6*CPAD; i += 128){
        int pp = i/CPAD, c = i - pp*CPAD;
        float v0 = 0.f, v1 = 0.f;
        if (c < CSZ){
            int gc = c0 + c;
            int b0 = 2*pp, b1 = b0 + 1;
            if (gc < 4608){
                int ch = gc/576, px = gc - ch*576;
                float r = sc[ch], t = sh[ch];
                v0 = fmaxf(g_h3[(b0*8+ch)*576 + px]*r + t, 0.f);
                v1 = fmaxf(g_h3[(b1*8+ch)*576 + px]*r + t, 0.f);
            } else if (gc < 4624){ int t = gc-4608; v0 = g_op[b0*16+t]; v1 = g_op[b1*16+t]; }
            else if (gc < 4640){   int t = gc-4624; v0 = g_om[b0*16+t]; v1 = g_om[b1*16+t]; }
            else if (gc < 4832){   int r = gc-4640; float o = g_op[r];
                                   v0 = vis[b0*12 + r/16]*o; v1 = vis[b1*12 + r/16]*o; }
            else                {  v0 = g_mm[gc-4832]; v1 = v0; }
        }
        ls[pp*LSTR + c] = pk2(v0, v1);
    }
    __syncthreads();
    const int warp = tid>>5, lane = tid&31;
    const int cb = 2*lane;
    const bool lane_full = (cb + 576 < CSZ);   // ii=9 col-overflow guard

    auto rowptr = [&](int pass)->const float* {
        int ridx = rblk*128 + pass*16 + warp*4;
        int gate = ridx / 4608;
        int gm = (gate==0) ? 0 : ((gate==1) ? 2 : 3);
        return w_ih + (size_t)(gm*4608 + (ridx - gate*4608))*INP + c0;
    };

    const float* wr = rowptr(0);
    float2 Wb[5][4];
    ldw(Wb[0], wr, cb,       true);
    ldw(Wb[1], wr, cb + 64,  true);
    ldw(Wb[2], wr, cb + 128, true);
    ldw(Wb[3], wr, cb + 192, true);

    for (int pass = 0; pass < 8; pass++){
        const float* wrn = (pass < 7) ? rowptr(pass+1) : wr;
        ull acc[4][6];
#pragma unroll
        for (int r = 0; r < 4; r++)
#pragma unroll
            for (int pp = 0; pp < 6; pp++) acc[r][pp] = 0ULL;
#pragma unroll
        for (int ii = 0; ii < 10; ii++){
            // prefetch global slot ii+4 (depth-4; wraps into next pass)
            {
                const int pii = ii + 4;
                const float* base = (pii < 10) ? wr : wrn;
                const int ii2 = (pii < 10) ? pii : (pii - 10);
                bool ok = (ii2 < 9) || lane_full;
                ldw(Wb[pii % 5], base, cb + 64*ii2, ok);
            }
            float2* W = Wb[ii % 5];
            const int c = cb + 64*ii;
            ull W0x = dup2(W[0].x), W0y = dup2(W[0].y);
            ull W1x = dup2(W[1].x), W1y = dup2(W[1].y);
            ull W2x = dup2(W[2].x), W2y = dup2(W[2].y);
            ull W3x = dup2(W[3].x), W3y = dup2(W[3].y);
#pragma unroll
            for (int pp = 0; pp < 6; pp++){
                ulonglong2 lv = *(const ulonglong2*)&ls[pp*LSTR + c];
                acc[0][pp] = fma2(W0x, lv.x, acc[0][pp]);
                acc[0][pp] = fma2(W0y, lv.y, acc[0][pp]);
                acc[1][pp] = fma2(W1x, lv.x, acc[1][pp]);
                acc[1][pp] = fma2(W1y, lv.y, acc[1][pp]);
                acc[2][pp] = fma2(W2x, lv.x, acc[2][pp]);
                acc[2][pp] = fma2(W2y, lv.y, acc[2][pp]);
                acc[3][pp] = fma2(W3x, lv.x, acc[3][pp]);
                acc[3][pp] = fma2(W3y, lv.y, acc[3][pp]);
            }
        }
        // reduce-scatter: fold rows over xor16 then xor8, butterfly remaining 6 ulls
        const bool hi16 = (lane & 16) != 0;
#pragma unroll
        for (int pp = 0; pp < 6; pp++){
            ull g0 = hi16 ? acc[0][pp] : acc[2][pp];
            ull g1 = hi16 ? acc[1][pp] : acc[3][pp];
            ull r0 = __shfl_xor_sync(0xffffffffu, g0, 16);
            ull r1 = __shfl_xor_sync(0xffffffffu, g1, 16);
            acc[0][pp] = add2(hi16 ? acc[2][pp] : acc[0][pp], r0);
            acc[1][pp] = add2(hi16 ? acc[3][pp] : acc[1][pp], r1);
        }
        const bool hi8 = (lane & 8) != 0;
#pragma unroll
        for (int pp = 0; pp < 6; pp++){
            ull g = hi8 ? acc[0][pp] : acc[1][pp];
            ull r = __shfl_xor_sync(0xffffffffu, g, 8);
            acc[0][pp] = add2(hi8 ? acc[1][pp] : acc[0][pp], r);
        }
#pragma unroll
        for (int off = 4; off; off >>= 1)
#pragma unroll
            for (int pp = 0; pp < 6; pp++)
                acc[0][pp] = add2(acc[0][pp], __shfl_xor_sync(0xffffffffu, acc[0][pp], off));
        {
            int local = lane & 7;
            int row_off = ((lane >> 3) & 1) + (((lane >> 4) & 1) << 1);
            if (local < 6){
                int rr = rblk*128 + pass*16 + warp*4 + row_off;
                *(ull*)&g_part[((size_t)chunk*13824 + rr)*KA + 2*local] = acc[0][local];
            }
        }
        wr = wrn;
    }
}

// ---------- sum partials + LSTM activations -> relu(h) agent-pair planes ----------
__global__ void k_fin(const float* __restrict__ b_ih, const float* __restrict__ b_hh){
    int idx = blockIdx.x*256 + threadIdx.x;
    if (idx >= KA*HSZ) return;
    int b = idx % KA, h = idx / KA;
    float si = b_ih[h] + b_hh[h];
    float sg = b_ih[9216 + h] + b_hh[9216 + h];
    float so = b_ih[13824 + h] + b_hh[13824 + h];
#pragma unroll
    for (int ch = 0; ch < NCH; ch++){
        const float* pp = g_part + (size_t)ch*13824*KA;
        si += pp[(size_t)h*KA + b];
        sg += pp[(size_t)(4608 + h)*KA + b];
        so += pp[(size_t)(9216 + h)*KA + b];
    }
    float c  = (1.f/(1.f + __expf(-si))) * tanhf(sg);
    float hv = (1.f/(1.f + __expf(-so))) * tanhf(c);
    g_hp[((size_t)(b>>1)*HSZ + h)*2 + (b&1)] = fmaxf(hv, 0.f);
}

// ---------- head GEMM (ah rows 0..127, inf rows 128..319) ----------
__global__ __launch_bounds__(128) void k_hgemm(const float* __restrict__ ah_w,
                                               const float* __restrict__ inf_w){
    __shared__ __align__(16) ull lsu[6*LSTR2];
    int rblk = blockIdx.x, chunk = blockIdx.y, tid = threadIdx.x;
    int c0 = chunk * CSZ2;
    const ull* gsrc = (const ull*)g_hp;
    for (int i = tid; i < 6*CSZ2; i += 128){
        int pp = i/CSZ2, c = i - pp*CSZ2;
        lsu[pp*LSTR2 + c] = gsrc[(size_t)pp*HSZ + c0 + c];
    }
    __syncthreads();
    int warp = tid>>5, lane = tid&31;
    int cb = 2*lane;
    int ridx = rblk*16 + warp*4;
    const float* __restrict__ wb = (ridx < 128) ? ah_w + (size_t)ridx*HSZ + c0
                                                : inf_w + (size_t)(ridx-128)*HSZ + c0;
    ull acc[4][6];
#pragma unroll
    for (int r = 0; r < 4; r++)
#pragma unroll
        for (int pp = 0; pp < 6; pp++) acc[r][pp] = 0ULL;
#pragma unroll
    for (int i = 0; i < 12; i++){
        int c = i*64 + cb;
        float2 wv0 = *(const float2*)(wb + c);
        float2 wv1 = *(const float2*)(wb + HSZ + c);
        float2 wv2 = *(const float2*)(wb + 2*HSZ + c);
        float2 wv3 = *(const float2*)(wb + 3*HSZ + c);
        ull W0x = dup2(wv0.x), W0y = dup2(wv0.y);
        ull W1x = dup2(wv1.x), W1y = dup2(wv1.y);
        ull W2x = dup2(wv2.x), W2y = dup2(wv2.y);
        ull W3x = dup2(wv3.x), W3y = dup2(wv3.y);
#pragma unroll
        for (int pp = 0; pp < 6; pp++){
            ulonglong2 lv = *(const ulonglong2*)&lsu[pp*LSTR2 + c];
            acc[0][pp] = fma2(W0x, lv.x, acc[0][pp]);
            acc[0][pp] = fma2(W0y, lv.y, acc[0][pp]);
            acc[1][pp] = fma2(W1x, lv.x, acc[1][pp]);
            acc[1][pp] = fma2(W1y, lv.y, acc[1][pp]);
            acc[2][pp] = fma2(W2x, lv.x, acc[2][pp]);
            acc[2][pp] = fma2(W2y, lv.y, acc[2][pp]);
            acc[3][pp] = fma2(W3x, lv.x, acc[3][pp]);
            acc[3][pp] = fma2(W3y, lv.y, acc[3][pp]);
        }
    }
#pragma unroll
    for (int r = 0; r < 4; r++)
#pragma unroll
        for (int pp = 0; pp < 6; pp++){
            ull v = acc[r][pp];
#pragma unroll
            for (int off = 16; off; off >>= 1)
                v = add2(v, __shfl_xor_sync(0xffffffffu, v, off));
            acc[r][pp] = v;
        }
    if (lane < 12){
        int pp = lane>>1, hi = lane&1;
#pragma unroll
        for (int r = 0; r < 4; r++){
            float lo_, hi_;
            asm("mov.b64 {%0,%1}, %2;" : "=f"(lo_), "=f"(hi_) : "l"(acc[r][pp]));
            g_part2[((size_t)chunk*HROWS + ridx + r)*KA + lane] = hi ? hi_ : lo_;
        }
    }
}

// ---------- head finalize + action head (single block) ----------
__global__ __launch_bounds__(512) void k_hfinact(const float* __restrict__ ah_b,
                                                 const float* __restrict__ inf_b,
                                                 const float* __restrict__ act_w,
                                                 const float* __restrict__ act_b,
                                                 float* __restrict__ out){
    __shared__ float t[12*128];
    int tid = threadIdx.x;
    for (int idx = tid; idx < HROWS*KA; idx += 512){
        int b = idx % KA, r = idx / KA;
        float s = (r < 128) ? ah_b[r] : inf_b[r-128];
#pragma unroll
        for (int ch = 0; ch < NCH2; ch++)
            s += g_part2[((size_t)ch*HROWS + r)*KA + b];
        if (r < 128) t[b*128 + r] = fmaxf(s, 0.f);
        else         out[192 + b*192 + (r-128)] = s;
    }
    __syncthreads();
    if (tid < 192){
        int b = tid/16, a = tid%16;
        float s = act_b[a];
        for (int q = 0; q < 128; q++) s += t[b*128+q] * act_w[a*128+q];
        out[b*16 + a] = s;
    }
}

extern "C" void kernel_launch(void* const* d_in, const int* in_sizes, int n_in,
                              void* d_out, int out_size){
    const float* x       = (const float*)d_in[0];
    const float* p       = (const float*)d_in[1];
    const float* m       = (const float*)d_in[2];
    const float* vis     = (const float*)d_in[3];
    const float* conv1_w = (const float*)d_in[4];
    const float* bn1_g   = (const float*)d_in[6];
    const float* bn1_b   = (const float*)d_in[7];
    const float* conv2_w = (const float*)d_in[8];
    const float* bn2_g   = (const float*)d_in[10];
    const float* bn2_b   = (const float*)d_in[11];
    const float* conv3_w = (const float*)d_in[12];
    const float* bn3_g   = (const float*)d_in[14];
    const float* bn3_b   = (const float*)d_in[15];
    const float* phys_w  = (const float*)d_in[16];
    const float* phys_b  = (const float*)d_in[17];
    const float* ment_w  = (const float*)d_in[18];
    const float* ment_b  = (const float*)d_in[19];
    const float* w_ih    = (const float*)d_in[20];   // w_hh (21) dead: h0 = 0
    const float* b_ih    = (const float*)d_in[22];
    const float* b_hh    = (const float*)d_in[23];
    const float* ah_w    = (const float*)d_in[24];
    const float* ah_b    = (const float*)d_in[25];
    const float* act_w   = (const float*)d_in[26];
    const float* act_b   = (const float*)d_in[27];
    const float* inf_w   = (const float*)d_in[28];
    const float* inf_b   = (const float*)d_in[29];
    float* out = (float*)d_out;

    k_conv1<<<dim3(12,6), 96>>>(x, conv1_w, p, m, phys_w, phys_b, ment_w, ment_b);  // 0
    k_conv2<<<dim3(12,6), 96>>>(conv2_w, bn1_g, bn1_b);                             // 1
    k_conv3<<<dim3(12,6), 96>>>(conv3_w, bn2_g, bn2_b);                             // 2
    k_gemm<<<dim3(NRB, NCH), 128>>>(w_ih, bn3_g, bn3_b, vis);                       // 3 <- ncu
    k_fin<<<216, 256>>>(b_ih, b_hh);                                                // 4
    k_hgemm<<<dim3(20, NCH2), 128>>>(ah_w, inf_w);                                  // 5
    k_hfinact<<<1, 512>>>(ah_b, inf_b, act_w, act_b, out);                          // 6
}

// round 9
// speedup vs baseline: 1.1251x; 1.1251x over previous
#include <cuda_runtime.h>
#include <math.h>
#include <stdint.h>

typedef unsigned long long ull;

#define KA 12
#define HSZ 4608
#define INP 5024
#define EPSB 1e-5f
#define NPX 6912.f

// big gemm tiling: 8 chunks x 628 cols, 54 row-blocks x 256 rows
#define CSZ 628
#define CPAD 640
#define LSTR 640
#define NCH 8
#define NRB 54
// head gemm tiling
#define CSZ2 768
#define LSTR2 770
#define NCH2 6
#define HROWS 320

// scratch
__device__ __align__(16) float g_h1[KA*16*576];
__device__ __align__(16) float g_h2[KA*16*576];
__device__ __align__(16) float g_h3[KA*8*576];
__device__ float g_p1[72*16*2];
__device__ float g_p2[72*16*2];
__device__ float g_p3[72*8*2];
__device__ float g_op[192], g_om[192], g_mm[192];
__device__ __align__(16) float g_part[(size_t)NCH*13824*KA];
__device__ __align__(16) float g_hp[6*HSZ*2];
__device__ __align__(16) float g_part2[(size_t)NCH2*HROWS*KA];

__device__ __forceinline__ ull pk2(float a, float b){ ull r; asm("mov.b64 %0,{%1,%2};":"=l"(r):"f"(a),"f"(b)); return r; }
__device__ __forceinline__ ull dup2(float a){ ull r; asm("mov.b64 %0,{%1,%1};":"=l"(r):"f"(a)); return r; }
__device__ __forceinline__ ull fma2(ull a, ull b, ull c){ ull d; asm("fma.rn.f32x2 %0,%1,%2,%3;":"=l"(d):"l"(a),"l"(b),"l"(c)); return d; }
__device__ __forceinline__ ull add2(ull a, ull b){ ull d; asm("add.rn.f32x2 %0,%1,%2;":"=l"(d):"l"(a),"l"(b)); return d; }
__device__ __forceinline__ uint32_t s2u(const void* p){
    uint32_t a; asm("{ .reg .u64 t; cvta.to.shared.u64 t, %1; cvt.u32.u64 %0, t; }":"=r"(a):"l"(p)); return a;
}

// ---------- conv1: 1x1 over (c,d) (bias cancels in BN) + stats; block(0,0) also agent linears ----------
__global__ __launch_bounds__(96) void k_conv1(const float* __restrict__ x,
                                              const float* __restrict__ w1,
                                              const float* __restrict__ p,  const float* __restrict__ m,
                                              const float* __restrict__ phys_w, const float* __restrict__ phys_b,
                                              const float* __restrict__ ment_w, const float* __restrict__ ment_b){
    __shared__ float ws[4096];
    __shared__ float sred[3][16][2];
    int b = blockIdx.x, strip = blockIdx.y, tid = threadIdx.x;
    int warp = tid>>5, lane = tid&31;
    for (int i = tid; i < 4096; i += 96) ws[i] = w1[i];
    __syncthreads();
    int px = strip*96 + tid;
    float acc[16];
#pragma unroll
    for (int o = 0; o < 16; o++) acc[o] = 0.f;
    const float* xb = x + (size_t)b*147456 + px;
#pragma unroll 16
    for (int cd = 0; cd < 256; cd++){
        float xv = xb[(size_t)cd*576];
#pragma unroll
        for (int o = 0; o < 16; o++) acc[o] += xv * ws[o*256+cd];
    }
#pragma unroll
    for (int o = 0; o < 16; o++) g_h1[((size_t)b*16+o)*576 + px] = acc[o];
#pragma unroll
    for (int o = 0; o < 16; o++){
        float s = acc[o], q = acc[o]*acc[o];
#pragma unroll
        for (int off = 16; off; off >>= 1){
            s += __shfl_xor_sync(0xffffffffu, s, off);
            q += __shfl_xor_sync(0xffffffffu, q, off);
        }
        if (lane == 0){ sred[warp][o][0] = s; sred[warp][o][1] = q; }
    }
    __syncthreads();
    if (tid < 16){
        int blk = b*6 + strip;
        g_p1[blk*32 + tid*2+0] = sred[0][tid][0]+sred[1][tid][0]+sred[2][tid][0];
        g_p1[blk*32 + tid*2+1] = sred[0][tid][1]+sred[1][tid][1]+sred[2][tid][1];
    }
    if (b == 0 && strip == 0){
        for (int i = tid; i < 192; i += 96){
            int j = i/16, t = i%16;
            float s1 = phys_b[t], s2 = ment_b[t], s3 = ment_b[t];
            for (int k = 0; k < 16; k++){
                s1 += p[j*16+k] * phys_w[t*16+k];
                float mv = m[j*16+k];
                s2 += mv * ment_w[t*16+k];
                s3 += 0.9f * mv * ment_w[t*16+k];
            }
            g_op[i] = fmaxf(s1, 0.f);
            g_om[i] = fmaxf(s2, 0.f);
            g_mm[i] = fmaxf(s3, 0.f);
        }
    }
}

// ---------- conv2: bn1 from partials + relu -> 3x3 SAME + stats (4-row strips) ----------
__global__ __launch_bounds__(96) void k_conv2(const float* __restrict__ w2,
                                              const float* __restrict__ g1,
                                              const float* __restrict__ bb1){
    __shared__ float in_s[16][6][24];
    __shared__ float ws[2304];
    __shared__ float sc[16], sh[16];
    __shared__ float sred[3][16][2];
    int b = blockIdx.x, ty = blockIdx.y, tid = threadIdx.x;
    int warp = tid>>5, lane = tid&31;
    if (tid < 16){
        float S = 0.f, Q = 0.f;
#pragma unroll
        for (int i = 0; i < 72; i++){ S += g_p1[i*32+tid*2]; Q += g_p1[i*32+tid*2+1]; }
        float mu = S/NPX, var = Q/NPX - mu*mu;
        float r = rsqrtf(var + EPSB) * g1[tid];
        sc[tid] = r; sh[tid] = bb1[tid] - mu*r;
    }
    for (int i = tid; i < 2304; i += 96) ws[i] = w2[i];
    __syncthreads();
    int r0 = 4*ty - 1;
    for (int i = tid; i < 16*6*24; i += 96){
        int ci = i/144, rr = (i/24)%6, cc = i%24;
        int gy = r0 + rr; float v = 0.f;
        if (gy >= 0 && gy < 24)
            v = fmaxf(g_h1[((size_t)b*16+ci)*576 + gy*24 + cc]*sc[ci] + sh[ci], 0.f);
        in_s[ci][rr][cc] = v;
    }
    __syncthreads();
    int ly = tid/24, lx = tid%24, gy = 4*ty + ly;
    float acc[16];
#pragma unroll
    for (int o = 0; o < 16; o++) acc[o] = 0.f;
    for (int ci = 0; ci < 16; ci++){
#pragma unroll
        for (int ky = 0; ky < 3; ky++){
#pragma unroll
            for (int kx = 0; kx < 3; kx++){
                int gx = lx + kx - 1;
                if (gx >= 0 && gx < 24){
                    float xv = in_s[ci][ly+ky][gx];
#pragma unroll
                    for (int o = 0; o < 16; o++) acc[o] += xv * ws[(o*16+ci)*9 + ky*3 + kx];
                }
            }
        }
    }
#pragma unroll
    for (int o = 0; o < 16; o++) g_h2[((size_t)b*16+o)*576 + gy*24 + lx] = acc[o];
#pragma unroll
    for (int o = 0; o < 16; o++){
        float s = acc[o], q = acc[o]*acc[o];
#pragma unroll
        for (int off = 16; off; off >>= 1){
            s += __shfl_xor_sync(0xffffffffu, s, off);
            q += __shfl_xor_sync(0xffffffffu, q, off);
        }
        if (lane == 0){ sred[warp][o][0] = s; sred[warp][o][1] = q; }
    }
    __syncthreads();
    if (tid < 16){
        int blk = b*6 + ty;
        g_p2[blk*32 + tid*2+0] = sred[0][tid][0]+sred[1][tid][0]+sred[2][tid][0];
        g_p2[blk*32 + tid*2+1] = sred[0][tid][1]+sred[1][tid][1]+sred[2][tid][1];
    }
}

// ---------- conv3: bn2 from partials + relu -> 5x5 SAME + stats (4-row strips) ----------
__global__ __launch_bounds__(96) void k_conv3(const float* __restrict__ w3,
                                              const float* __restrict__ g2,
                                              const float* __restrict__ bb2){
    __shared__ float in_s[16][8][24];
    __shared__ float ws[3200];
    __shared__ float sc[16], sh[16];
    __shared__ float sred[3][8][2];
    int b = blockIdx.x, ty = blockIdx.y, tid = threadIdx.x;
    int warp = tid>>5, lane = tid&31;
    if (tid < 16){
        float S = 0.f, Q = 0.f;
#pragma unroll
        for (int i = 0; i < 72; i++){ S += g_p2[i*32+tid*2]; Q += g_p2[i*32+tid*2+1]; }
        float mu = S/NPX, var = Q/NPX - mu*mu;
        float r = rsqrtf(var + EPSB) * g2[tid];
        sc[tid] = r; sh[tid] = bb2[tid] - mu*r;
    }
    for (int i = tid; i < 3200; i += 96) ws[i] = w3[i];
    __syncthreads();
    int r0 = 4*ty - 2;
    for (int i = tid; i < 16*8*24; i += 96){
        int ci = i/192, rr = (i/24)%8, cc = i%24;
        int gy = r0 + rr; float v = 0.f;
        if (gy >= 0 && gy < 24)
            v = fmaxf(g_h2[((size_t)b*16+ci)*576 + gy*24 + cc]*sc[ci] + sh[ci], 0.f);
        in_s[ci][rr][cc] = v;
    }
    __syncthreads();
    int ly = tid/24, lx = tid%24, gy = 4*ty + ly;
    float acc[8];
#pragma unroll
    for (int o = 0; o < 8; o++) acc[o] = 0.f;
    for (int ci = 0; ci < 16; ci++){
#pragma unroll
        for (int ky = 0; ky < 5; ky++){
#pragma unroll
            for (int kx = 0; kx < 5; kx++){
                int gx = lx + kx - 2;
                if (gx >= 0 && gx < 24){
                    float xv = in_s[ci][ly+ky][gx];
#pragma unroll
                    for (int o = 0; o < 8; o++) acc[o] += xv * ws[(o*16+ci)*25 + ky*5 + kx];
                }
            }
        }
    }
#pragma unroll
    for (int o = 0; o < 8; o++) g_h3[((size_t)b*8+o)*576 + gy*24 + lx] = acc[o];
#pragma unroll
    for (int o = 0; o < 8; o++){
        float s = acc[o], q = acc[o]*acc[o];
#pragma unroll
        for (int off = 16; off; off >>= 1){
            s += __shfl_xor_sync(0xffffffffu, s, off);
            q += __shfl_xor_sync(0xffffffffu, q, off);
        }
        if (lane == 0){ sred[warp][o][0] = s; sred[warp][o][1] = q; }
    }
    __syncthreads();
    if (tid < 8){
        int blk = b*6 + ty;
        g_p3[blk*16 + tid*2+0] = sred[0][tid][0]+sred[1][tid][0]+sred[2][tid][0];
        g_p3[blk*16 + tid*2+1] = sred[0][tid][1]+sred[1][tid][1]+sred[2][tid][1];
    }
}

// ---------- big weight-streaming GEMM (i,g,o rows; f gate dead since c0=0) ----------
// grid (54, 8) x 128 thr, 256 rows/block = 16 passes x 4 warps x 4 rows.
// Weights staged through a per-warp-private 4-deep cp.async smem ring (lane self-copy:
// lane l writes bytes 8l of each row and only reads those bytes back -> no barriers).
__global__ __launch_bounds__(128, 4) void k_gemm(
    const float* __restrict__ w_ih, const float* __restrict__ g3,
    const float* __restrict__ bb3,  const float* __restrict__ vis)
{
    __shared__ __align__(16) ull ls[6*LSTR];            // 30720 B activations
    __shared__ __align__(16) float wsm[4][4][4][64];    // [warp][slot][row][col] 16384 B
    __shared__ float sc[8], sh[8];
    const int rblk = blockIdx.x, chunk = blockIdx.y, tid = threadIdx.x;
    const int c0 = chunk * CSZ;
    if (tid < 8){
        float S = 0.f, Q = 0.f;
#pragma unroll
        for (int i = 0; i < 72; i++){ S += g_p3[i*16+tid*2]; Q += g_p3[i*16+tid*2+1]; }
        float mu = S/NPX, var = Q/NPX - mu*mu;
        float r = rsqrtf(var + EPSB) * g3[tid];
        sc[tid] = r; sh[tid] = bb3[tid] - mu*r;
    }
    __syncthreads();
    // fill: agent-pair-packed lstm_in slice, zero pad for c >= CSZ
    for (int i = tid; i < 6*CPAD; i += 128){
        int pp = i/CPAD, c = i - pp*CPAD;
        float v0 = 0.f, v1 = 0.f;
        if (c < CSZ){
            int gc = c0 + c;
            int b0 = 2*pp, b1 = b0 + 1;
            if (gc < 4608){
                int ch = gc/576, px = gc - ch*576;
                float r = sc[ch], t = sh[ch];
                v0 = fmaxf(g_h3[(b0*8+ch)*576 + px]*r + t, 0.f);
                v1 = fmaxf(g_h3[(b1*8+ch)*576 + px]*r + t, 0.f);
            } else if (gc < 4624){ int t = gc-4608; v0 = g_op[b0*16+t]; v1 = g_op[b1*16+t]; }
            else if (gc < 4640){   int t = gc-4624; v0 = g_om[b0*16+t]; v1 = g_om[b1*16+t]; }
            else if (gc < 4832){   int r = gc-4640; float o = g_op[r];
                                   v0 = vis[b0*12 + r/16]*o; v1 = vis[b1*12 + r/16]*o; }
            else                {  v0 = g_mm[gc-4832]; v1 = v0; }
        }
        ls[pp*LSTR + c] = pk2(v0, v1);
    }
    __syncthreads();
    const int warp = tid>>5, lane = tid&31;
    const int cl = 2*lane;                         // lane's 2-col offset within a 64-col tile
    const uint32_t wbase = s2u(&wsm[warp][0][0][0]);

    // issue stage g: 4 rows x 8B per lane (cp.async.ca self-copy)
    auto issue = [&](int g){
        int pass = g/10, ii = g - pass*10;
        int ridx = rblk*256 + pass*16 + warp*4;
        int gate = ridx / 4608;
        int gm = (gate==0) ? 0 : ((gate==1) ? 2 : 3);
        const float* wr = w_ih + (size_t)(gm*4608 + ridx - gate*4608)*INP + c0;
        int col = ii*64 + cl; if (col > 626) col = 626;   // clamp (act is 0 there)
        uint32_t s = wbase + (uint32_t)((g & 3)*1024 + cl*4);
#pragma unroll
        for (int r = 0; r < 4; r++)
            asm volatile("cp.async.ca.shared.global [%0], [%1], 8;"
                         :: "r"(s + r*256), "l"(wr + (size_t)r*INP + col));
        asm volatile("cp.async.commit_group;");
    };

    issue(0); issue(1); issue(2); issue(3);

    for (int pass = 0; pass < 16; pass++){
        ull acc[4][6];
#pragma unroll
        for (int r = 0; r < 4; r++)
#pragma unroll
            for (int pp = 0; pp < 6; pp++) acc[r][pp] = 0ULL;
#pragma unroll 2
        for (int ii = 0; ii < 10; ii++){
            const int g = pass*10 + ii;
            asm volatile("cp.async.wait_group 3;");
            // read this lane's weights for 4 rows from the ring slot
            uint32_t s = wbase + (uint32_t)((g & 3)*1024 + cl*4);
            float2 W[4];
#pragma unroll
            for (int r = 0; r < 4; r++)
                asm volatile("ld.shared.v2.f32 {%0,%1}, [%2];"
                             : "=f"(W[r].x), "=f"(W[r].y) : "r"(s + r*256));
            // refill: stage g+4 (or empty commit to keep group accounting aligned)
            if (g + 4 < 160) issue(g + 4);
            else asm volatile("cp.async.commit_group;");
            const int c = ii*64 + cl;
            ull W0x = dup2(W[0].x), W0y = dup2(W[0].y);
            ull W1x = dup2(W[1].x), W1y = dup2(W[1].y);
            ull W2x = dup2(W[2].x), W2y = dup2(W[2].y);
            ull W3x = dup2(W[3].x), W3y = dup2(W[3].y);
#pragma unroll
            for (int pp = 0; pp < 6; pp++){
                ulonglong2 lv = *(const ulonglong2*)&ls[pp*LSTR + c];
                acc[0][pp] = fma2(W0x, lv.x, acc[0][pp]);
                acc[0][pp] = fma2(W0y, lv.y, acc[0][pp]);
                acc[1][pp] = fma2(W1x, lv.x, acc[1][pp]);
                acc[1][pp] = fma2(W1y, lv.y, acc[1][pp]);
                acc[2][pp] = fma2(W2x, lv.x, acc[2][pp]);
                acc[2][pp] = fma2(W2y, lv.y, acc[2][pp]);
                acc[3][pp] = fma2(W3x, lv.x, acc[3][pp]);
                acc[3][pp] = fma2(W3y, lv.y, acc[3][pp]);
            }
        }
        // reduce-scatter: fold rows over xor16 then xor8, butterfly remaining 6 ulls
        const int lane_ = lane;
        const bool hi16 = (lane_ & 16) != 0;
#pragma unroll
        for (int pp = 0; pp < 6; pp++){
            ull g0 = hi16 ? acc[0][pp] : acc[2][pp];
            ull g1 = hi16 ? acc[1][pp] : acc[3][pp];
            ull r0 = __shfl_xor_sync(0xffffffffu, g0, 16);
            ull r1 = __shfl_xor_sync(0xffffffffu, g1, 16);
            acc[0][pp] = add2(hi16 ? acc[2][pp] : acc[0][pp], r0);
            acc[1][pp] = add2(hi16 ? acc[3][pp] : acc[1][pp], r1);
        }
        const bool hi8 = (lane_ & 8) != 0;
#pragma unroll
        for (int pp = 0; pp < 6; pp++){
            ull g = hi8 ? acc[0][pp] : acc[1][pp];
            ull r = __shfl_xor_sync(0xffffffffu, g, 8);
            acc[0][pp] = add2(hi8 ? acc[1][pp] : acc[0][pp], r);
        }
#pragma unroll
        for (int off = 4; off; off >>= 1)
#pragma unroll
            for (int pp = 0; pp < 6; pp++)
                acc[0][pp] = add2(acc[0][pp], __shfl_xor_sync(0xffffffffu, acc[0][pp], off));
        {
            int local = lane_ & 7;
            int row_off = ((lane_ >> 3) & 1) + (((lane_ >> 4) & 1) << 1);
            if (local < 6){
                int rr = rblk*256 + pass*16 + warp*4 + row_off;
                *(ull*)&g_part[((size_t)chunk*13824 + rr)*KA + 2*local] = acc[0][local];
            }
        }
    }
    asm volatile("cp.async.wait_group 0;");
}

// ---------- sum partials + LSTM activations -> relu(h) agent-pair planes ----------
__global__ void k_fin(const float* __restrict__ b_ih, const float* __restrict__ b_hh){
    int idx = blockIdx.x*256 + threadIdx.x;
    if (idx >= KA*HSZ) return;
    int b = idx % KA, h = idx / KA;
    float si = b_ih[h] + b_hh[h];
    float sg = b_ih[9216 + h] + b_hh[9216 + h];
    float so = b_ih[13824 + h] + b_hh[13824 + h];
#pragma unroll
    for (int ch = 0; ch < NCH; ch++){
        const float* pp = g_part + (size_t)ch*13824*KA;
        si += pp[(size_t)h*KA + b];
        sg += pp[(size_t)(4608 + h)*KA + b];
        so += pp[(size_t)(9216 + h)*KA + b];
    }
    float c  = (1.f/(1.f + __expf(-si))) * tanhf(sg);
    float hv = (1.f/(1.f + __expf(-so))) * tanhf(c);
    g_hp[((size_t)(b>>1)*HSZ + h)*2 + (b&1)] = fmaxf(hv, 0.f);
}

// ---------- head GEMM (ah rows 0..127, inf rows 128..319) ----------
__global__ __launch_bounds__(128) void k_hgemm(const float* __restrict__ ah_w,
                                               const float* __restrict__ inf_w){
    __shared__ __align__(16) ull lsu[6*LSTR2];
    int rblk = blockIdx.x, chunk = blockIdx.y, tid = threadIdx.x;
    int c0 = chunk * CSZ2;
    const ull* gsrc = (const ull*)g_hp;
    for (int i = tid; i < 6*CSZ2; i += 128){
        int pp = i/CSZ2, c = i - pp*CSZ2;
        lsu[pp*LSTR2 + c] = gsrc[(size_t)pp*HSZ + c0 + c];
    }
    __syncthreads();
    int warp = tid>>5, lane = tid&31;
    int cb = 2*lane;
    int ridx = rblk*16 + warp*4;
    const float* __restrict__ wb = (ridx < 128) ? ah_w + (size_t)ridx*HSZ + c0
                                                : inf_w + (size_t)(ridx-128)*HSZ + c0;
    ull acc[4][6];
#pragma unroll
    for (int r = 0; r < 4; r++)
#pragma unroll
        for (int pp = 0; pp < 6; pp++) acc[r][pp] = 0ULL;
#pragma unroll
    for (int i = 0; i < 12; i++){
        int c = i*64 + cb;
        float2 wv0 = *(const float2*)(wb + c);
        float2 wv1 = *(const float2*)(wb + HSZ + c);
        float2 wv2 = *(const float2*)(wb + 2*HSZ + c);
        float2 wv3 = *(const float2*)(wb + 3*HSZ + c);
        ull W0x = dup2(wv0.x), W0y = dup2(wv0.y);
        ull W1x = dup2(wv1.x), W1y = dup2(wv1.y);
        ull W2x = dup2(wv2.x), W2y = dup2(wv2.y);
        ull W3x = dup2(wv3.x), W3y = dup2(wv3.y);
#pragma unroll
        for (int pp = 0; pp < 6; pp++){
            ulonglong2 lv = *(const ulonglong2*)&lsu[pp*LSTR2 + c];
            acc[0][pp] = fma2(W0x, lv.x, acc[0][pp]);
            acc[0][pp] = fma2(W0y, lv.y, acc[0][pp]);
            acc[1][pp] = fma2(W1x, lv.x, acc[1][pp]);
            acc[1][pp] = fma2(W1y, lv.y, acc[1][pp]);
            acc[2][pp] = fma2(W2x, lv.x, acc[2][pp]);
            acc[2][pp] = fma2(W2y, lv.y, acc[2][pp]);
            acc[3][pp] = fma2(W3x, lv.x, acc[3][pp]);
            acc[3][pp] = fma2(W3y, lv.y, acc[3][pp]);
        }
    }
#pragma unroll
    for (int r = 0; r < 4; r++)
#pragma unroll
        for (int pp = 0; pp < 6; pp++){
            ull v = acc[r][pp];
#pragma unroll
            for (int off = 16; off; off >>= 1)
                v = add2(v, __shfl_xor_sync(0xffffffffu, v, off));
            acc[r][pp] = v;
        }
    if (lane < 12){
        int pp = lane>>1, hi = lane&1;
#pragma unroll
        for (int r = 0; r < 4; r++){
            float lo_, hi_;
            asm("mov.b64 {%0,%1}, %2;" : "=f"(lo_), "=f"(hi_) : "l"(acc[r][pp]));
            g_part2[((size_t)chunk*HROWS + ridx + r)*KA + lane] = hi ? hi_ : lo_;
        }
    }
}

// ---------- head finalize + action head (single block) ----------
__global__ __launch_bounds__(512) void k_hfinact(const float* __restrict__ ah_b,
                                                 const float* __restrict__ inf_b,
                                                 const float* __restrict__ act_w,
                                                 const float* __restrict__ act_b,
                                                 float* __restrict__ out){
    __shared__ float t[12*128];
    int tid = threadIdx.x;
    for (int idx = tid; idx < HROWS*KA; idx += 512){
        int b = idx % KA, r = idx / KA;
        float s = (r < 128) ? ah_b[r] : inf_b[r-128];
#pragma unroll
        for (int ch = 0; ch < NCH2; ch++)
            s += g_part2[((size_t)ch*HROWS + r)*KA + b];
        if (r < 128) t[b*128 + r] = fmaxf(s, 0.f);
        else         out[192 + b*192 + (r-128)] = s;
    }
    __syncthreads();
    if (tid < 192){
        int b = tid/16, a = tid%16;
        float s = act_b[a];
        for (int q = 0; q < 128; q++) s += t[b*128+q] * act_w[a*128+q];
        out[b*16 + a] = s;
    }
}

extern "C" void kernel_launch(void* const* d_in, const int* in_sizes, int n_in,
                              void* d_out, int out_size){
    const float* x       = (const float*)d_in[0];
    const float* p       = (const float*)d_in[1];
    const float* m       = (const float*)d_in[2];
    const float* vis     = (const float*)d_in[3];
    const float* conv1_w = (const float*)d_in[4];
    const float* bn1_g   = (const float*)d_in[6];
    const float* bn1_b   = (const float*)d_in[7];
    const float* conv2_w = (const float*)d_in[8];
    const float* bn2_g   = (const float*)d_in[10];
    const float* bn2_b   = (const float*)d_in[11];
    const float* conv3_w = (const float*)d_in[12];
    const float* bn3_g   = (const float*)d_in[14];
    const float* bn3_b   = (const float*)d_in[15];
    const float* phys_w  = (const float*)d_in[16];
    const float* phys_b  = (const float*)d_in[17];
    const float* ment_w  = (const float*)d_in[18];
    const float* ment_b  = (const float*)d_in[19];
    const float* w_ih    = (const float*)d_in[20];   // w_hh (21) dead: h0 = 0
    const float* b_ih    = (const float*)d_in[22];
    const float* b_hh    = (const float*)d_in[23];
    const float* ah_w    = (const float*)d_in[24];
    const float* ah_b    = (const float*)d_in[25];
    const float* act_w   = (const float*)d_in[26];
    const float* act_b   = (const float*)d_in[27];
    const float* inf_w   = (const float*)d_in[28];
    const float* inf_b   = (const float*)d_in[29];
    float* out = (float*)d_out;

    k_conv1<<<dim3(12,6), 96>>>(x, conv1_w, p, m, phys_w, phys_b, ment_w, ment_b);  // 0
    k_conv2<<<dim3(12,6), 96>>>(conv2_w, bn1_g, bn1_b);                             // 1
    k_conv3<<<dim3(12,6), 96>>>(conv3_w, bn2_g, bn2_b);                             // 2
    k_gemm<<<dim3(NRB, NCH), 128>>>(w_ih, bn3_g, bn3_b, vis);                       // 3 <- ncu
    k_fin<<<216, 256>>>(b_ih, b_hh);                                                // 4
    k_hgemm<<<dim3(20, NCH2), 128>>>(ah_w, inf_w);                                  // 5
    k_hfinact<<<1, 512>>>(ah_b, inf_b, act_w, act_b, out);                          // 6
}